// round 15
// baseline (speedup 1.0000x reference)
#include <cuda_runtime.h>

// NonMaximaSuppression2d: x (8,32,512,512) fp32.
// m = max over 8 neighbors (replicate pad), floored at 0 (zeroed center tap).
// out = x * (x > m).
// R14: persistent grid-stride over the R9-optimal tile body.
//   R9 body: RPT=4, 6-row window fully front-batched (6 LDG.128 + edge
//   scalars on the same lines), launch_bounds(128,12), plain stores.
//   Change: launch exactly 152*12=1824 CTAs (one wave on GB300's 152 SMs);
//   each CTA grid-strides over the 32768 tiles. Kills 17 wave transitions,
//   the 0.45-fraction tail wave, and 32768->1824 CTA prologues. Stride
//   assignment keeps concurrent tiles contiguous (L2 halo sharing intact).

#define HH 512
#define WW 512
#define RPT 4           // rows per output strip
#define NROWS (RPT + 2) // 6 rows in the window
#define TPB 128         // threads per block = WW/4 float4 groups
#define NSM 152
#define CPS 12          // CTAs per SM
#define NTILES_TOTAL (256 * (HH / RPT))   // 32768

struct RowRegs {
    float4 v;   // 4 center values
    float  l;   // value at col-1 (replicated at left edge)
    float  r;   // value at col+4 (replicated at right edge)
};

__device__ __forceinline__ void load_row(const float* __restrict__ img,
                                         int y, int c, RowRegs& rr) {
    int yc = min(max(y, 0), HH - 1);
    const float* p = img + (size_t)yc * WW + c;
    rr.v = *reinterpret_cast<const float4*>(p);
    // edge scalars hit the same 128B lines as neighbor lanes' vectors -> L1
    rr.l = (c > 0)      ? __ldg(p - 1) : rr.v.x;
    rr.r = (c + 4 < WW) ? __ldg(p + 4) : rr.v.w;
}

// max of 3 horizontally adjacent values per lane (rows above/below)
__device__ __forceinline__ float4 hmax3(const RowRegs& rr) {
    float4 h;
    h.x = fmaxf(fmaxf(rr.l,   rr.v.x), rr.v.y);
    h.y = fmaxf(fmaxf(rr.v.x, rr.v.y), rr.v.z);
    h.z = fmaxf(fmaxf(rr.v.y, rr.v.z), rr.v.w);
    h.w = fmaxf(fmaxf(rr.v.z, rr.v.w), rr.r);
    return h;
}

// max of the 2 horizontal neighbors (center excluded; for the center row)
__device__ __forceinline__ float4 hmax2(const RowRegs& rr) {
    float4 h;
    h.x = fmaxf(rr.l,   rr.v.y);
    h.y = fmaxf(rr.v.x, rr.v.z);
    h.z = fmaxf(rr.v.y, rr.v.w);
    h.w = fmaxf(rr.v.z, rr.r);
    return h;
}

__global__ __launch_bounds__(TPB, CPS)
void nms2d_kernel(const float* __restrict__ x, float* __restrict__ out) {
    const int tiles_per_img = HH / RPT;             // 128
    const int c = threadIdx.x * 4;                  // 0..508

    for (int t = blockIdx.x; t < NTILES_TOTAL; t += gridDim.x) {
        const int img  = t / tiles_per_img;
        const int tile = t % tiles_per_img;

        const float* in = x   + (size_t)img * HH * WW;
        float*       o  = out + (size_t)img * HH * WW;
        const int y0 = tile * RPT;

        // front-batch the entire 6-row window: 6 independent LDG.128
        // (+ edge scalars riding the same in-flight lines)
        RowRegs w[NROWS];
        #pragma unroll
        for (int k = 0; k < NROWS; k++)
            load_row(in, y0 - 1 + k, c, w[k]);

        float* op = o + (size_t)y0 * WW + c;

        #pragma unroll
        for (int i = 0; i < RPT; i++) {
            float4 mp = hmax3(w[i]);
            float4 mc = hmax2(w[i + 1]);
            float4 mn = hmax3(w[i + 2]);

            // fold the zeroed-center-tap floor (reference inits max at 0)
            float4 m;
            m.x = fmaxf(fmaxf(fmaxf(mp.x, mc.x), mn.x), 0.0f);
            m.y = fmaxf(fmaxf(fmaxf(mp.y, mc.y), mn.y), 0.0f);
            m.z = fmaxf(fmaxf(fmaxf(mp.z, mc.z), mn.z), 0.0f);
            m.w = fmaxf(fmaxf(fmaxf(mp.w, mc.w), mn.w), 0.0f);

            float4 xc = w[i + 1].v;
            float4 r;
            r.x = (xc.x > m.x) ? xc.x : 0.0f;
            r.y = (xc.y > m.y) ? xc.y : 0.0f;
            r.z = (xc.z > m.z) ? xc.z : 0.0f;
            r.w = (xc.w > m.w) ? xc.w : 0.0f;

            *reinterpret_cast<float4*>(op) = r;
            op += WW;
        }
    }
}

extern "C" void kernel_launch(void* const* d_in, const int* in_sizes, int n_in,
                              void* d_out, int out_size) {
    const float* x = (const float*)d_in[0];
    float* out = (float*)d_out;

    nms2d_kernel<<<NSM * CPS, TPB>>>(x, out);   // 1824 CTAs = one wave
}

// round 16
// speedup vs baseline: 1.2306x; 1.2306x over previous
#include <cuda_runtime.h>

// NonMaximaSuppression2d: x (8,32,512,512) fp32.
// m = max over 8 neighbors (replicate pad), floored at 0 (zeroed center tap).
// out = x * (x > m).
// FINAL (= R9 config, unique measured optimum):
//   RPT=4, 6-row window fully front-batched (6 independent LDG.128 with edge
//   scalars riding the same in-flight 128B lines), launch_bounds(128,12) ->
//   regs=40, 12 CTAs/SM, ~288 outstanding loads/SM, plain write-back stores,
//   launch-indexed grid (hardware CTA scheduling provides inter-tile
//   pipelining; persistent grid-stride loses it: 99.8us).
// Measured: 75.7us ncu / 80.4us wall, 6404 GB/s (80% DRAM), traffic at the
// ~490MB read+write floor. All neighboring configs measured worse:
//   RPT {32,16,8,4,2} -> {86.0,87.2,79.4,78.0,84.9}us ncu; 10-row batch
//   spills (134us); 13-CTA reg cap serializes the batch; shuffle halos bind
//   on issue (55%); deferred strided halos bind on L1 (90%); stcs neutral.

#define HH 512
#define WW 512
#define RPT 4           // rows per output strip
#define NROWS (RPT + 2) // 6 rows in the window
#define TPB 128         // threads per block = WW/4 float4 groups

struct RowRegs {
    float4 v;   // 4 center values
    float  l;   // value at col-1 (replicated at left edge)
    float  r;   // value at col+4 (replicated at right edge)
};

__device__ __forceinline__ void load_row(const float* __restrict__ img,
                                         int y, int c, RowRegs& rr) {
    int yc = min(max(y, 0), HH - 1);
    const float* p = img + (size_t)yc * WW + c;
    rr.v = *reinterpret_cast<const float4*>(p);
    // edge scalars hit the same 128B lines as neighbor lanes' vectors -> L1
    rr.l = (c > 0)      ? __ldg(p - 1) : rr.v.x;
    rr.r = (c + 4 < WW) ? __ldg(p + 4) : rr.v.w;
}

// max of 3 horizontally adjacent values per lane (rows above/below)
__device__ __forceinline__ float4 hmax3(const RowRegs& rr) {
    float4 h;
    h.x = fmaxf(fmaxf(rr.l,   rr.v.x), rr.v.y);
    h.y = fmaxf(fmaxf(rr.v.x, rr.v.y), rr.v.z);
    h.z = fmaxf(fmaxf(rr.v.y, rr.v.z), rr.v.w);
    h.w = fmaxf(fmaxf(rr.v.z, rr.v.w), rr.r);
    return h;
}

// max of the 2 horizontal neighbors (center excluded; for the center row)
__device__ __forceinline__ float4 hmax2(const RowRegs& rr) {
    float4 h;
    h.x = fmaxf(rr.l,   rr.v.y);
    h.y = fmaxf(rr.v.x, rr.v.z);
    h.z = fmaxf(rr.v.y, rr.v.w);
    h.w = fmaxf(rr.v.z, rr.r);
    return h;
}

__global__ __launch_bounds__(TPB, 12)
void nms2d_kernel(const float* __restrict__ x, float* __restrict__ out) {
    const int tiles_per_img = HH / RPT;             // 128
    const int img  = blockIdx.x / tiles_per_img;
    const int tile = blockIdx.x % tiles_per_img;

    const float* in = x   + (size_t)img * HH * WW;
    float*       o  = out + (size_t)img * HH * WW;

    const int c  = threadIdx.x * 4;                 // 0..508
    const int y0 = tile * RPT;

    // front-batch the entire 6-row window: 6 independent LDG.128 (+ edge
    // scalars interleaved, riding the same in-flight lines)
    RowRegs w[NROWS];
    #pragma unroll
    for (int k = 0; k < NROWS; k++)
        load_row(in, y0 - 1 + k, c, w[k]);

    float* op = o + (size_t)y0 * WW + c;

    #pragma unroll
    for (int i = 0; i < RPT; i++) {
        float4 mp = hmax3(w[i]);
        float4 mc = hmax2(w[i + 1]);
        float4 mn = hmax3(w[i + 2]);

        // fold the zeroed-center-tap floor (reference inits max at 0)
        float4 m;
        m.x = fmaxf(fmaxf(fmaxf(mp.x, mc.x), mn.x), 0.0f);
        m.y = fmaxf(fmaxf(fmaxf(mp.y, mc.y), mn.y), 0.0f);
        m.z = fmaxf(fmaxf(fmaxf(mp.z, mc.z), mn.z), 0.0f);
        m.w = fmaxf(fmaxf(fmaxf(mp.w, mc.w), mn.w), 0.0f);

        float4 xc = w[i + 1].v;
        float4 r;
        r.x = (xc.x > m.x) ? xc.x : 0.0f;
        r.y = (xc.y > m.y) ? xc.y : 0.0f;
        r.z = (xc.z > m.z) ? xc.z : 0.0f;
        r.w = (xc.w > m.w) ? xc.w : 0.0f;

        *reinterpret_cast<float4*>(op) = r;
        op += WW;
    }
}

extern "C" void kernel_launch(void* const* d_in, const int* in_sizes, int n_in,
                              void* d_out, int out_size) {
    const float* x = (const float*)d_in[0];
    float* out = (float*)d_out;

    const int n_img = in_sizes[0] / (HH * WW);      // B*C = 256
    const int blocks = n_img * (HH / RPT);          // 32768

    nms2d_kernel<<<blocks, TPB>>>(x, out);
}